// round 1
// baseline (speedup 1.0000x reference)
#include <cuda_runtime.h>
#include <cuda_bf16.h>
#include <math.h>

// Problem constants
#define BB_   2
#define TT_   2048
#define HID_  2048
#define HH_   16
#define DH_   128
#define KD_   2048          // H*Dh
#define MM_   (BB_*TT_)     // 4096
#define KCONV 4

// ---------------- scratch (device globals; no allocation APIs) ----------------
__device__ float g_qpre[MM_*KD_];
__device__ float g_kpre[MM_*KD_];
__device__ float g_vpre[MM_*KD_];
__device__ float g_gbuf[MM_*KD_];
__device__ float g_qr [MM_*KD_];
__device__ float g_kr [MM_*KD_];
__device__ float g_vc [MM_*KD_];
__device__ float g_act[MM_*KD_];
__device__ float g_beta [MM_*HH_];
__device__ float g_alpha[MM_*HH_];

// ---------------- 128x128x16 smem-tiled SGEMM (row-major A,B,C) ----------------
// A: M x K, B: K x N, C: M x N. M%128==0, N%128==0, K%16==0 (true for all calls).
__global__ __launch_bounds__(256)
void gemm_kernel(const float* __restrict__ A, const float* __restrict__ B,
                 float* __restrict__ C, int M, int N, int K)
{
    __shared__ float As[16][128];
    __shared__ float Bs[16][128];

    const int tid = threadIdx.x;
    const int bx = blockIdx.x, by = blockIdx.y;
    const int tx = tid & 15, ty = tid >> 4;

    const float* Ab = A + (size_t)by * 128 * K;
    const float* Bb = B + (size_t)bx * 128;

    const int f0 = tid * 2;
    const int f1 = f0 + 1;
    const int a0r = f0 >> 2, a0k = (f0 & 3) * 4;
    const int a1r = f1 >> 2, a1k = (f1 & 3) * 4;
    const int b0r = f0 >> 5, b0n = (f0 & 31) * 4;
    const int b1r = f1 >> 5, b1n = (f1 & 31) * 4;

    float4 ra0, ra1, rb0, rb1;
    ra0 = *(const float4*)(Ab + (size_t)a0r * K + a0k);
    ra1 = *(const float4*)(Ab + (size_t)a1r * K + a1k);
    rb0 = *(const float4*)(Bb + (size_t)b0r * N + b0n);
    rb1 = *(const float4*)(Bb + (size_t)b1r * N + b1n);

    float acc[8][8];
    #pragma unroll
    for (int i = 0; i < 8; i++)
        #pragma unroll
        for (int j = 0; j < 8; j++) acc[i][j] = 0.f;

    for (int k0 = 0; k0 < K; k0 += 16) {
        // stage current tile to smem (A transposed)
        As[a0k+0][a0r] = ra0.x; As[a0k+1][a0r] = ra0.y;
        As[a0k+2][a0r] = ra0.z; As[a0k+3][a0r] = ra0.w;
        As[a1k+0][a1r] = ra1.x; As[a1k+1][a1r] = ra1.y;
        As[a1k+2][a1r] = ra1.z; As[a1k+3][a1r] = ra1.w;
        *(float4*)&Bs[b0r][b0n] = rb0;
        *(float4*)&Bs[b1r][b1n] = rb1;
        __syncthreads();

        int kn = k0 + 16;
        if (kn < K) { // prefetch next tile (hidden under compute)
            ra0 = *(const float4*)(Ab + (size_t)a0r * K + kn + a0k);
            ra1 = *(const float4*)(Ab + (size_t)a1r * K + kn + a1k);
            rb0 = *(const float4*)(Bb + (size_t)(kn + b0r) * N + b0n);
            rb1 = *(const float4*)(Bb + (size_t)(kn + b1r) * N + b1n);
        }

        #pragma unroll
        for (int kk = 0; kk < 16; kk++) {
            float a[8], b[8];
            *(float4*)(a)     = *(const float4*)&As[kk][ty*8];
            *(float4*)(a + 4) = *(const float4*)&As[kk][ty*8 + 4];
            *(float4*)(b)     = *(const float4*)&Bs[kk][tx*8];
            *(float4*)(b + 4) = *(const float4*)&Bs[kk][tx*8 + 4];
            #pragma unroll
            for (int i = 0; i < 8; i++)
                #pragma unroll
                for (int j = 0; j < 8; j++)
                    acc[i][j] = fmaf(a[i], b[j], acc[i][j]);
        }
        __syncthreads();
    }

    float* Cb = C + (size_t)(by*128 + ty*8) * N + bx*128 + tx*8;
    #pragma unroll
    for (int i = 0; i < 8; i++) {
        *(float4*)(Cb + (size_t)i * N)     = make_float4(acc[i][0], acc[i][1], acc[i][2], acc[i][3]);
        *(float4*)(Cb + (size_t)i * N + 4) = make_float4(acc[i][4], acc[i][5], acc[i][6], acc[i][7]);
    }
}

// ---------------- beta / alpha (x@Wb, x@Wgk fused, N=16 each) ----------------
__global__ __launch_bounds__(256)
void bg_kernel(const float* __restrict__ x,
               const float* __restrict__ Wb,  const float* __restrict__ bb,
               const float* __restrict__ Wgk, const float* __restrict__ bgk,
               const float* __restrict__ A_log, const float* __restrict__ dt_bias,
               float* __restrict__ beta, float* __restrict__ alpha)
{
    const int warp = threadIdx.x >> 5;
    const int lane = threadIdx.x & 31;
    const int m = blockIdx.x * 8 + warp;
    const float* xr = x + (size_t)m * HID_;
    const float* W  = (lane < 16) ? Wb : Wgk;
    const int c = lane & 15;

    float acc0 = 0.f, acc1 = 0.f;
    for (int kk = 0; kk < HID_; kk += 4) {
        float4 xv = *(const float4*)(xr + kk);
        acc0 = fmaf(xv.x, W[(kk + 0) * HH_ + c], acc0);
        acc1 = fmaf(xv.y, W[(kk + 1) * HH_ + c], acc1);
        acc0 = fmaf(xv.z, W[(kk + 2) * HH_ + c], acc0);
        acc1 = fmaf(xv.w, W[(kk + 3) * HH_ + c], acc1);
    }
    float acc = acc0 + acc1;
    if (lane < 16) {
        beta[(size_t)m * HH_ + c] = 1.f / (1.f + expf(-(acc + bb[c])));
    } else {
        float vv = acc + bgk[c] + dt_bias[c];
        float sp = fmaxf(vv, 0.f) + log1pf(expf(-fabsf(vv)));   // softplus, stable
        alpha[(size_t)m * HH_ + c] = expf(-expf(A_log[c]) * sp);
    }
}

// ---------------- causal depthwise conv(K=4) + SiLU (for v) ----------------
__global__ __launch_bounds__(256)
void conv_silu_kernel(const float* __restrict__ pre, const float* __restrict__ w,
                      const float* __restrict__ bias, float* __restrict__ out)
{
    size_t idx = (size_t)blockIdx.x * 256 + threadIdx.x;   // over MM_*KD_
    int c = (int)(idx & (KD_ - 1));
    size_t m = idx >> 11;
    int t = (int)(m & (TT_ - 1));
    int b = (int)(m >> 11);
    const float* pb = pre + ((size_t)b * TT_) * KD_ + c;
    float acc = bias[c];
    #pragma unroll
    for (int j = 0; j < KCONV; j++) {
        int tt = t - (KCONV - 1) + j;
        if (tt >= 0) acc = fmaf(pb[(size_t)tt * KD_], w[c * KCONV + j], acc);
    }
    out[idx] = acc / (1.f + expf(-acc));
}

// ---------------- conv + SiLU + RoPE + L2 norm (for q and k) ----------------
__global__ __launch_bounds__(128)
void conv_rope_kernel(const float* __restrict__ pre, const float* __restrict__ w,
                      const float* __restrict__ bias, float* __restrict__ out)
{
    __shared__ float sv[DH_];
    __shared__ float swarp[4];
    const int bid = blockIdx.x;            // b*T*H + t*H + h
    const int h = bid & (HH_ - 1);
    const int bt = bid >> 4;
    const int t = bt & (TT_ - 1);
    const int b = bt >> 11;
    const int d = threadIdx.x;
    const int c = h * DH_ + d;

    const float* pb = pre + ((size_t)b * TT_) * KD_ + c;
    float acc = bias[c];
    #pragma unroll
    for (int j = 0; j < KCONV; j++) {
        int tt = t - (KCONV - 1) + j;
        if (tt >= 0) acc = fmaf(pb[(size_t)tt * KD_], w[c * KCONV + j], acc);
    }
    sv[d] = acc / (1.f + expf(-acc));
    __syncthreads();

    const int i = d & 63;
    float x1 = sv[2 * i], x2 = sv[2 * i + 1];
    const int fidx = (2 * i) & 63;                       // reference's (2i) % 64 quirk
    float inv = exp2f(-(float)fidx * (13.287712379549449f / 64.0f)); // 10000^(-fidx/64)
    float th = (float)t * inv;
    float cs = cosf(th), sn = sinf(th);
    float r = (d < 64) ? (x1 * cs - x2 * sn) : (x1 * sn + x2 * cs);

    float ss = r * r;
    #pragma unroll
    for (int off = 16; off; off >>= 1) ss += __shfl_down_sync(0xffffffffu, ss, off);
    if ((d & 31) == 0) swarp[d >> 5] = ss;
    __syncthreads();
    float tot = swarp[0] + swarp[1] + swarp[2] + swarp[3];
    float nrm = fmaxf(sqrtf(tot), 1e-12f);
    out[((size_t)(b * TT_ + t) * HH_ + h) * DH_ + d] = r / nrm;
}

// ---------------- sequential gated-delta scan + fused output norm/gate ----------------
// One CTA per (b,h). S[128][128] in registers (8x8 per thread, 256 threads).
__global__ __launch_bounds__(256)
void scan_kernel(const float* __restrict__ q, const float* __restrict__ k,
                 const float* __restrict__ v, const float* __restrict__ g,
                 const float* __restrict__ alpha, const float* __restrict__ beta,
                 const float* __restrict__ Dp, const float* __restrict__ onw,
                 float* __restrict__ act)
{
    __shared__ float sq[DH_], sk[DH_], sv[DH_], sg[DH_], sw[DH_];
    __shared__ float red_o[16 * DH_];
    __shared__ float red_s[16 * DH_];
    __shared__ float s_sk[DH_];
    __shared__ float s_qk[4], s_rms[4], s_ab[2];

    const int tid = threadIdx.x;
    const int bh = blockIdx.x;
    const int h = bh & (HH_ - 1);
    const int b = bh >> 4;
    const int tx = tid & 15, ty = tid >> 4;
    const int dbase = ty * 8, ebase = tx * 8;

    float S[8][8];
    #pragma unroll
    for (int i = 0; i < 8; i++)
        #pragma unroll
        for (int j = 0; j < 8; j++) S[i][j] = 0.f;

    if (tid < DH_) sw[tid] = onw[tid];
    const float Dph = Dp[h];
    const size_t vecbase = ((size_t)(b * TT_) * HH_ + h) * DH_;

    for (int t = 0; t < TT_; t++) {
        const size_t base = vecbase + (size_t)t * (HH_ * DH_);
        if (tid < DH_) {
            sq[tid] = q[base + tid];
            sk[tid] = k[base + tid];
            sv[tid] = v[base + tid];
            sg[tid] = g[base + tid];
        }
        if (tid == 0) {
            size_t si = (size_t)(b * TT_ + t) * HH_ + h;
            s_ab[0] = alpha[si];
            s_ab[1] = beta[si];
        }
        __syncthreads();                       // (1) vectors ready

        float qv[8], kv[8];
        #pragma unroll
        for (int i = 0; i < 8; i++) qv[i] = sq[dbase + i];
        #pragma unroll
        for (int j = 0; j < 8; j++) kv[j] = sk[ebase + j];

        float po[8] = {0,0,0,0,0,0,0,0};
        float ps[8] = {0,0,0,0,0,0,0,0};
        #pragma unroll
        for (int i = 0; i < 8; i++) {
            float qi = qv[i];
            #pragma unroll
            for (int j = 0; j < 8; j++) {
                float s = S[i][j];
                po[j] = fmaf(qi, s, po[j]);       // o partial: sum_d q_d S[d,e]
                ps[i] = fmaf(s, kv[j], ps[i]);    // Sk partial: sum_e S[d,e] k_e
            }
        }
        #pragma unroll
        for (int j = 0; j < 8; j++) red_o[ty * DH_ + ebase + j] = po[j];
        #pragma unroll
        for (int i = 0; i < 8; i++) red_s[tx * DH_ + dbase + i] = ps[i];
        __syncthreads();                       // (2) partials staged

        float o = 0.f;
        if (tid < DH_) {
            float skd = 0.f;
            #pragma unroll
            for (int xx = 0; xx < 16; xx++) {
                o   += red_o[xx * DH_ + tid];
                skd += red_s[xx * DH_ + tid];
            }
            s_sk[tid] = skd;
            float qq = sq[tid] * sk[tid];
            #pragma unroll
            for (int off = 16; off; off >>= 1) qq += __shfl_down_sync(0xffffffffu, qq, off);
            if ((tid & 31) == 0) s_qk[tid >> 5] = qq;
        }
        __syncthreads();                       // (3) Sk + qk ready

        const float aA = s_ab[0];
        const float bB = s_ab[1];

        if (tid < DH_) {
            float qkv = s_qk[0] + s_qk[1] + s_qk[2] + s_qk[3];
            o = fmaf(Dph * qkv, sv[tid], o);
            float oo = o * o;
            #pragma unroll
            for (int off = 16; off; off >>= 1) oo += __shfl_down_sync(0xffffffffu, oo, off);
            if ((tid & 31) == 0) s_rms[tid >> 5] = oo;
        }

        // state update: S = aA*S + (bB*v_d - aA*bB*Sk_d) * k_e
        float cf[8];
        #pragma unroll
        for (int i = 0; i < 8; i++)
            cf[i] = bB * sv[dbase + i] - aA * bB * s_sk[dbase + i];
        #pragma unroll
        for (int i = 0; i < 8; i++) {
            float c = cf[i];
            #pragma unroll
            for (int j = 0; j < 8; j++)
                S[i][j] = fmaf(aA, S[i][j], c * kv[j]);
        }
        __syncthreads();                       // (4) rms staged, update done

        if (tid < DH_) {
            float rsum = s_rms[0] + s_rms[1] + s_rms[2] + s_rms[3];
            float rr = rsqrtf(rsum * (1.f / (float)DH_) + 1e-6f);
            float valn = o * rr * sw[tid];
            float sig = 1.f / (1.f + expf(-valn));
            act[base + tid] = sg[tid] * valn * sig;
        }
    }
}

// ---------------- launch ----------------
extern "C" void kernel_launch(void* const* d_in, const int* in_sizes, int n_in,
                              void* d_out, int out_size)
{
    const float* x       = (const float*)d_in[0];
    const float* Wq      = (const float*)d_in[1];
    const float* Wk      = (const float*)d_in[2];
    const float* Wv      = (const float*)d_in[3];
    const float* Wg      = (const float*)d_in[4];
    const float* Wo      = (const float*)d_in[5];
    const float* Wb      = (const float*)d_in[6];
    const float* bb      = (const float*)d_in[7];
    const float* Wgk     = (const float*)d_in[8];
    const float* bgk     = (const float*)d_in[9];
    const float* cqw     = (const float*)d_in[10];
    const float* cqb     = (const float*)d_in[11];
    const float* ckw     = (const float*)d_in[12];
    const float* ckb     = (const float*)d_in[13];
    const float* cvw     = (const float*)d_in[14];
    const float* cvb     = (const float*)d_in[15];
    const float* A_log   = (const float*)d_in[16];
    const float* Dp      = (const float*)d_in[17];
    const float* dt_bias = (const float*)d_in[18];
    const float* onorm_w = (const float*)d_in[19];

    float *qpre, *kpre, *vpre, *gbuf, *qr, *kr, *vc, *act, *beta, *alpha;
    cudaGetSymbolAddress((void**)&qpre,  g_qpre);
    cudaGetSymbolAddress((void**)&kpre,  g_kpre);
    cudaGetSymbolAddress((void**)&vpre,  g_vpre);
    cudaGetSymbolAddress((void**)&gbuf,  g_gbuf);
    cudaGetSymbolAddress((void**)&qr,    g_qr);
    cudaGetSymbolAddress((void**)&kr,    g_kr);
    cudaGetSymbolAddress((void**)&vc,    g_vc);
    cudaGetSymbolAddress((void**)&act,   g_act);
    cudaGetSymbolAddress((void**)&beta,  g_beta);
    cudaGetSymbolAddress((void**)&alpha, g_alpha);

    dim3 gg(KD_ / 128, MM_ / 128);
    gemm_kernel<<<gg, 256>>>(x, Wq, qpre, MM_, KD_, HID_);
    gemm_kernel<<<gg, 256>>>(x, Wk, kpre, MM_, KD_, HID_);
    gemm_kernel<<<gg, 256>>>(x, Wv, vpre, MM_, KD_, HID_);
    gemm_kernel<<<gg, 256>>>(x, Wg, gbuf, MM_, KD_, HID_);

    bg_kernel<<<MM_ / 8, 256>>>(x, Wb, bb, Wgk, bgk, A_log, dt_bias, beta, alpha);

    conv_rope_kernel<<<BB_ * TT_ * HH_, 128>>>(qpre, cqw, cqb, qr);
    conv_rope_kernel<<<BB_ * TT_ * HH_, 128>>>(kpre, ckw, ckb, kr);
    conv_silu_kernel<<<(MM_ * KD_) / 256, 256>>>(vpre, cvw, cvb, vc);

    scan_kernel<<<BB_ * HH_, 256>>>(qr, kr, vc, gbuf, alpha, beta, Dp, onorm_w, act);

    gemm_kernel<<<dim3(HID_ / 128, MM_ / 128), 256>>>(act, Wo, (float*)d_out, MM_, HID_, KD_);
}

// round 5
// speedup vs baseline: 1.7839x; 1.7839x over previous
#include <cuda_runtime.h>
#include <cuda_bf16.h>
#include <math.h>
#include <stdint.h>

// Problem constants
#define BB_   2
#define TT_   2048
#define HID_  2048
#define HH_   16
#define DH_   128
#define KD_   2048          // H*Dh
#define MM_   (BB_*TT_)     // 4096
#define KCONV 4

// ---------------- scratch (device globals; no allocation APIs) ----------------
__device__ float g_qpre[MM_*KD_];
__device__ float g_kpre[MM_*KD_];
__device__ float g_vpre[MM_*KD_];
__device__ float g_gbuf[MM_*KD_];
__device__ float g_qr [MM_*KD_];
__device__ float g_kr [MM_*KD_];
__device__ float g_vc [MM_*KD_];
__device__ float g_act[MM_*KD_];
__device__ float g_xr [MM_*HID_];      // tf32-rounded x
__device__ float g_beta [MM_*HH_];
__device__ float g_alpha[MM_*HH_];
__device__ float g_wt[5 * KD_ * HID_]; // transposed + tf32-rounded weights

// ---------------- helpers ----------------
__device__ __forceinline__ uint32_t smem_u32(const void* p) {
    uint32_t a;
    asm("{ .reg .u64 t; cvta.to.shared.u64 t, %1; cvt.u32.u64 %0, t; }" : "=r"(a) : "l"(p));
    return a;
}
__device__ __forceinline__ float cvt_tf32(float x) {
    uint32_t y;
    asm("cvt.rna.tf32.f32 %0, %1;" : "=r"(y) : "f"(x));
    return __uint_as_float(y);
}
__device__ __forceinline__ void cp_async16(uint32_t dst, const void* src) {
    asm volatile("cp.async.cg.shared.global [%0], [%1], 16;" :: "r"(dst), "l"(src) : "memory");
}
__device__ __forceinline__ void cp_commit() {
    asm volatile("cp.async.commit_group;" ::: "memory");
}
__device__ __forceinline__ void mma_tf32_16n8k8(float* c, const uint32_t* a, const uint32_t* b) {
    asm volatile(
        "mma.sync.aligned.m16n8k8.row.col.f32.tf32.tf32.f32 "
        "{%0,%1,%2,%3}, {%4,%5,%6,%7}, {%8,%9}, {%0,%1,%2,%3};"
        : "+f"(c[0]), "+f"(c[1]), "+f"(c[2]), "+f"(c[3])
        : "r"(a[0]), "r"(a[1]), "r"(a[2]), "r"(a[3]), "r"(b[0]), "r"(b[1]));
}

// ---------------- elementwise tf32 rounding (x -> xr) ----------------
__global__ __launch_bounds__(256)
void cvt_kernel(const float* __restrict__ in, float* __restrict__ out)
{
    size_t i = ((size_t)blockIdx.x * 256 + threadIdx.x) * 4;
    float4 v = *(const float4*)(in + i);
    v.x = cvt_tf32(v.x); v.y = cvt_tf32(v.y);
    v.z = cvt_tf32(v.z); v.w = cvt_tf32(v.w);
    *(float4*)(out + i) = v;
}

// ---------------- weight transpose + tf32 rounding (2048x2048) ----------------
__global__ __launch_bounds__(256)
void transpose_cvt(const float* __restrict__ W, float* __restrict__ Wt, int K, int N)
{
    __shared__ float t[32][33];
    const int k0 = blockIdx.y * 32, n0 = blockIdx.x * 32;
    const int x = threadIdx.x, y = threadIdx.y;    // (32, 8)
    #pragma unroll
    for (int j = 0; j < 32; j += 8)
        t[y + j][x] = W[(size_t)(k0 + y + j) * N + n0 + x];
    __syncthreads();
    #pragma unroll
    for (int j = 0; j < 32; j += 8)
        Wt[(size_t)(n0 + y + j) * K + k0 + x] = cvt_tf32(t[x][y + j]);
}

// ---------------- tf32 mma.sync GEMM: C[M,N] = A[M,K] @ Bt[N,K]^T ----------------
// CTA tile 128x128, K chunks of 32, cp.async double-buffered SMEM.
// 8 warps = 2(M) x 4(N); warp tile 64x32 = 4x4 m16n8k8 fragments.
#define GPAD 36
#define GBUF_FLOATS (128 * GPAD)                 // one operand buffer
#define GBUF_BYTES  (GBUF_FLOATS * 4)            // 18432
#define GSTAGE_BYTES (2 * GBUF_BYTES)            // A+B per stage: 36864
#define GEMM_SMEM (2 * GSTAGE_BYTES)             // double buffer: 73728

__global__ __launch_bounds__(256, 2)
void gemm_tc(const float* __restrict__ A, const float* __restrict__ Bt,
             float* __restrict__ C, int M, int N, int K)
{
    extern __shared__ __align__(128) char dynsmem[];
    const uint32_t sbase = smem_u32(dynsmem);
    const int tid = threadIdx.x;
    const int wid = tid >> 5, lane = tid & 31;
    const int gid = lane >> 2, tig = lane & 3;     // group id / thread-in-group
    const int wm = wid >> 2, wn = wid & 3;         // warp 2x4 grid
    const int bx = blockIdx.x, by = blockIdx.y;

    const float* Ab = A  + (size_t)by * 128 * K;
    const float* Bb = Bt + (size_t)bx * 128 * K;

    float acc[4][4][4];
    #pragma unroll
    for (int mt = 0; mt < 4; mt++)
        #pragma unroll
        for (int nt = 0; nt < 4; nt++)
            #pragma unroll
            for (int r = 0; r < 4; r++) acc[mt][nt][r] = 0.f;

    const int row = tid >> 3, c4 = (tid & 7) * 4;          // staging coords
    const uint32_t stoff = (uint32_t)(row * GPAD + c4) * 4;

    const int nchunk = K >> 5;                              // K/32

    // stage chunk 0 into buffer 0
    {
        const float* Ak = Ab;
        const float* Bk = Bb;
        #pragma unroll
        for (int u = 0; u < 4; u++) {
            uint32_t d = sbase + stoff + (uint32_t)(u * 32 * GPAD * 4);
            cp_async16(d,              Ak + (size_t)(row + u * 32) * K + c4);
            cp_async16(d + GBUF_BYTES, Bk + (size_t)(row + u * 32) * K + c4);
        }
        cp_commit();
    }

    for (int i = 0; i < nchunk; i++) {
        const int buf = i & 1;
        if (i + 1 < nchunk) {
            const int nb = buf ^ 1;
            const float* Ak = Ab + (i + 1) * 32;
            const float* Bk = Bb + (i + 1) * 32;
            #pragma unroll
            for (int u = 0; u < 4; u++) {
                uint32_t d = sbase + (uint32_t)nb * GSTAGE_BYTES + stoff
                           + (uint32_t)(u * 32 * GPAD * 4);
                cp_async16(d,              Ak + (size_t)(row + u * 32) * K + c4);
                cp_async16(d + GBUF_BYTES, Bk + (size_t)(row + u * 32) * K + c4);
            }
            cp_commit();
            asm volatile("cp.async.wait_group 1;" ::: "memory");
        } else {
            asm volatile("cp.async.wait_group 0;" ::: "memory");
        }
        __syncthreads();

        const float* As = (const float*)(dynsmem + (size_t)buf * GSTAGE_BYTES);
        const float* Bs = As + GBUF_FLOATS;

        #pragma unroll
        for (int s = 0; s < 4; s++) {
            const int k0 = s * 8;
            uint32_t afrag[4][4];
            #pragma unroll
            for (int mt = 0; mt < 4; mt++) {
                const int m0 = wm * 64 + mt * 16 + gid;
                afrag[mt][0] = __float_as_uint(As[(m0)     * GPAD + k0 + tig]);
                afrag[mt][1] = __float_as_uint(As[(m0 + 8) * GPAD + k0 + tig]);
                afrag[mt][2] = __float_as_uint(As[(m0)     * GPAD + k0 + tig + 4]);
                afrag[mt][3] = __float_as_uint(As[(m0 + 8) * GPAD + k0 + tig + 4]);
            }
            uint32_t bfrag[4][2];
            #pragma unroll
            for (int nt = 0; nt < 4; nt++) {
                const int n0 = wn * 32 + nt * 8 + gid;
                bfrag[nt][0] = __float_as_uint(Bs[n0 * GPAD + k0 + tig]);
                bfrag[nt][1] = __float_as_uint(Bs[n0 * GPAD + k0 + tig + 4]);
            }
            #pragma unroll
            for (int mt = 0; mt < 4; mt++)
                #pragma unroll
                for (int nt = 0; nt < 4; nt++)
                    mma_tf32_16n8k8(acc[mt][nt], afrag[mt], bfrag[nt]);
        }
        __syncthreads();
    }

    // epilogue
    #pragma unroll
    for (int mt = 0; mt < 4; mt++) {
        const int r0 = by * 128 + wm * 64 + mt * 16 + gid;
        #pragma unroll
        for (int nt = 0; nt < 4; nt++) {
            const int cc = bx * 128 + wn * 32 + nt * 8 + tig * 2;
            *(float2*)(C + (size_t)r0 * N + cc)       = make_float2(acc[mt][nt][0], acc[mt][nt][1]);
            *(float2*)(C + (size_t)(r0 + 8) * N + cc) = make_float2(acc[mt][nt][2], acc[mt][nt][3]);
        }
    }
}

// ---------------- beta / alpha (x@Wb, x@Wgk fused, N=16 each) ----------------
__global__ __launch_bounds__(256)
void bg_kernel(const float* __restrict__ x,
               const float* __restrict__ Wb,  const float* __restrict__ bb,
               const float* __restrict__ Wgk, const float* __restrict__ bgk,
               const float* __restrict__ A_log, const float* __restrict__ dt_bias,
               float* __restrict__ beta, float* __restrict__ alpha)
{
    const int warp = threadIdx.x >> 5;
    const int lane = threadIdx.x & 31;
    const int m = blockIdx.x * 8 + warp;
    const float* xr = x + (size_t)m * HID_;
    const float* W  = (lane < 16) ? Wb : Wgk;
    const int c = lane & 15;

    float acc0 = 0.f, acc1 = 0.f;
    for (int kk = 0; kk < HID_; kk += 4) {
        float4 xv = *(const float4*)(xr + kk);
        acc0 = fmaf(xv.x, W[(kk + 0) * HH_ + c], acc0);
        acc1 = fmaf(xv.y, W[(kk + 1) * HH_ + c], acc1);
        acc0 = fmaf(xv.z, W[(kk + 2) * HH_ + c], acc0);
        acc1 = fmaf(xv.w, W[(kk + 3) * HH_ + c], acc1);
    }
    float acc = acc0 + acc1;
    if (lane < 16) {
        beta[(size_t)m * HH_ + c] = 1.f / (1.f + expf(-(acc + bb[c])));
    } else {
        float vv = acc + bgk[c] + dt_bias[c];
        float sp = fmaxf(vv, 0.f) + log1pf(expf(-fabsf(vv)));   // softplus, stable
        alpha[(size_t)m * HH_ + c] = expf(-expf(A_log[c]) * sp);
    }
}

// ---------------- causal depthwise conv(K=4) + SiLU (for v) ----------------
__global__ __launch_bounds__(256)
void conv_silu_kernel(const float* __restrict__ pre, const float* __restrict__ w,
                      const float* __restrict__ bias, float* __restrict__ out)
{
    size_t idx = (size_t)blockIdx.x * 256 + threadIdx.x;   // over MM_*KD_
    int c = (int)(idx & (KD_ - 1));
    size_t m = idx >> 11;
    int t = (int)(m & (TT_ - 1));
    int b = (int)(m >> 11);
    const float* pb = pre + ((size_t)b * TT_) * KD_ + c;
    float acc = bias[c];
    #pragma unroll
    for (int j = 0; j < KCONV; j++) {
        int tt = t - (KCONV - 1) + j;
        if (tt >= 0) acc = fmaf(pb[(size_t)tt * KD_], w[c * KCONV + j], acc);
    }
    out[idx] = acc / (1.f + expf(-acc));
}

// ---------------- conv + SiLU + RoPE + L2 norm (for q and k) ----------------
__global__ __launch_bounds__(128)
void conv_rope_kernel(const float* __restrict__ pre, const float* __restrict__ w,
                      const float* __restrict__ bias, float* __restrict__ out)
{
    __shared__ float sv[DH_];
    __shared__ float swarp[4];
    const int bid = blockIdx.x;            // b*T*H + t*H + h
    const int h = bid & (HH_ - 1);
    const int bt = bid >> 4;
    const int t = bt & (TT_ - 1);
    const int b = bt >> 11;
    const int d = threadIdx.x;
    const int c = h * DH_ + d;

    const float* pb = pre + ((size_t)b * TT_) * KD_ + c;
    float acc = bias[c];
    #pragma unroll
    for (int j = 0; j < KCONV; j++) {
        int tt = t - (KCONV - 1) + j;
        if (tt >= 0) acc = fmaf(pb[(size_t)tt * KD_], w[c * KCONV + j], acc);
    }
    sv[d] = acc / (1.f + expf(-acc));
    __syncthreads();

    const int i = d & 63;
    float x1 = sv[2 * i], x2 = sv[2 * i + 1];
    const int fidx = (2 * i) & 63;                       // reference's (2i) % 64 quirk
    float inv = exp2f(-(float)fidx * (13.287712379549449f / 64.0f)); // 10000^(-fidx/64)
    float th = (float)t * inv;
    float cs = cosf(th), sn = sinf(th);
    float r = (d < 64) ? (x1 * cs - x2 * sn) : (x1 * sn + x2 * cs);

    float ss = r * r;
    #pragma unroll
    for (int off = 16; off; off >>= 1) ss += __shfl_down_sync(0xffffffffu, ss, off);
    if ((d & 31) == 0) swarp[d >> 5] = ss;
    __syncthreads();
    float tot = swarp[0] + swarp[1] + swarp[2] + swarp[3];
    float nrm = fmaxf(sqrtf(tot), 1e-12f);
    out[((size_t)(b * TT_ + t) * HH_ + h) * DH_ + d] = r / nrm;
}

// ---------------- sequential gated-delta scan + fused output norm/gate ----------------
__global__ __launch_bounds__(256)
void scan_kernel(const float* __restrict__ q, const float* __restrict__ k,
                 const float* __restrict__ v, const float* __restrict__ g,
                 const float* __restrict__ alpha, const float* __restrict__ beta,
                 const float* __restrict__ Dp, const float* __restrict__ onw,
                 float* __restrict__ act)
{
    __shared__ float sq[DH_], sk[DH_], sv[DH_], sg[DH_], sw[DH_];
    __shared__ float red_o[16 * DH_];
    __shared__ float red_s[16 * DH_];
    __shared__ float s_sk[DH_];
    __shared__ float s_qk[4], s_rms[4], s_ab[2];

    const int tid = threadIdx.x;
    const int bh = blockIdx.x;
    const int h = bh & (HH_ - 1);
    const int b = bh >> 4;
    const int tx = tid & 15, ty = tid >> 4;
    const int dbase = ty * 8, ebase = tx * 8;

    float S[8][8];
    #pragma unroll
    for (int i = 0; i < 8; i++)
        #pragma unroll
        for (int j = 0; j < 8; j++) S[i][j] = 0.f;

    if (tid < DH_) sw[tid] = onw[tid];
    const float Dph = Dp[h];
    const size_t vecbase = ((size_t)(b * TT_) * HH_ + h) * DH_;

    for (int t = 0; t < TT_; t++) {
        const size_t base = vecbase + (size_t)t * (HH_ * DH_);
        if (tid < DH_) {
            sq[tid] = q[base + tid];
            sk[tid] = k[base + tid];
            sv[tid] = v[base + tid];
            sg[tid] = g[base + tid];
        }
        if (tid == 0) {
            size_t si = (size_t)(b * TT_ + t) * HH_ + h;
            s_ab[0] = alpha[si];
            s_ab[1] = beta[si];
        }
        __syncthreads();

        float qv[8], kv[8];
        #pragma unroll
        for (int i = 0; i < 8; i++) qv[i] = sq[dbase + i];
        #pragma unroll
        for (int j = 0; j < 8; j++) kv[j] = sk[ebase + j];

        float po[8] = {0,0,0,0,0,0,0,0};
        float ps[8] = {0,0,0,0,0,0,0,0};
        #pragma unroll
        for (int i = 0; i < 8; i++) {
            float qi = qv[i];
            #pragma unroll
            for (int j = 0; j < 8; j++) {
                float s = S[i][j];
                po[j] = fmaf(qi, s, po[j]);
                ps[i] = fmaf(s, kv[j], ps[i]);
            }
        }
        #pragma unroll
        for (int j = 0; j < 8; j++) red_o[ty * DH_ + ebase + j] = po[j];
        #pragma unroll
        for (int i = 0; i < 8; i++) red_s[tx * DH_ + dbase + i] = ps[i];
        __syncthreads();

        float o = 0.f;
        if (tid < DH_) {
            float skd = 0.f;
            #pragma unroll
            for (int xx = 0; xx < 16; xx++) {
                o   += red_o[xx * DH_ + tid];
                skd += red_s[xx * DH_ + tid];
            }
            s_sk[tid] = skd;
            float qq = sq[tid] * sk[tid];
            #pragma unroll
            for (int off = 16; off; off >>= 1) qq += __shfl_down_sync(0xffffffffu, qq, off);
            if ((tid & 31) == 0) s_qk[tid >> 5] = qq;
        }
        __syncthreads();

        const float aA = s_ab[0];
        const float bB = s_ab[1];

        if (tid < DH_) {
            float qkv = s_qk[0] + s_qk[1] + s_qk[2] + s_qk[3];
            o = fmaf(Dph * qkv, sv[tid], o);
            float oo = o * o;
            #pragma unroll
            for (int off = 16; off; off >>= 1) oo += __shfl_down_sync(0xffffffffu, oo, off);
            if ((tid & 31) == 0) s_rms[tid >> 5] = oo;
        }

        float cf[8];
        #pragma unroll
        for (int i = 0; i < 8; i++)
            cf[i] = bB * sv[dbase + i] - aA * bB * s_sk[dbase + i];
        #pragma unroll
        for (int i = 0; i < 8; i++) {
            float c = cf[i];
            #pragma unroll
            for (int j = 0; j < 8; j++)
                S[i][j] = fmaf(aA, S[i][j], c * kv[j]);
        }
        __syncthreads();

        if (tid < DH_) {
            float rsum = s_rms[0] + s_rms[1] + s_rms[2] + s_rms[3];
            float rr = rsqrtf(rsum * (1.f / (float)DH_) + 1e-6f);
            float valn = o * rr * sw[tid];
            float sig = 1.f / (1.f + expf(-valn));
            // tf32-round here: this buffer is the A operand of the Wo GEMM
            act[base + tid] = cvt_tf32(sg[tid] * valn * sig);
        }
    }
}

// ---------------- launch ----------------
extern "C" void kernel_launch(void* const* d_in, const int* in_sizes, int n_in,
                              void* d_out, int out_size)
{
    const float* x       = (const float*)d_in[0];
    const float* Wq      = (const float*)d_in[1];
    const float* Wk      = (const float*)d_in[2];
    const float* Wv      = (const float*)d_in[3];
    const float* Wg      = (const float*)d_in[4];
    const float* Wo      = (const float*)d_in[5];
    const float* Wb      = (const float*)d_in[6];
    const float* bb      = (const float*)d_in[7];
    const float* Wgk     = (const float*)d_in[8];
    const float* bgk     = (const float*)d_in[9];
    const float* cqw     = (const float*)d_in[10];
    const float* cqb     = (const float*)d_in[11];
    const float* ckw     = (const float*)d_in[12];
    const float* ckb     = (const float*)d_in[13];
    const float* cvw     = (const float*)d_in[14];
    const float* cvb     = (const float*)d_in[15];
    const float* A_log   = (const float*)d_in[16];
    const float* Dp      = (const float*)d_in[17];
    const float* dt_bias = (const float*)d_in[18];
    const float* onorm_w = (const float*)d_in[19];

    float *qpre, *kpre, *vpre, *gbuf, *qr, *kr, *vc, *act, *xr, *beta, *alpha, *wt;
    cudaGetSymbolAddress((void**)&qpre,  g_qpre);
    cudaGetSymbolAddress((void**)&kpre,  g_kpre);
    cudaGetSymbolAddress((void**)&vpre,  g_vpre);
    cudaGetSymbolAddress((void**)&gbuf,  g_gbuf);
    cudaGetSymbolAddress((void**)&qr,    g_qr);
    cudaGetSymbolAddress((void**)&kr,    g_kr);
    cudaGetSymbolAddress((void**)&vc,    g_vc);
    cudaGetSymbolAddress((void**)&act,   g_act);
    cudaGetSymbolAddress((void**)&xr,    g_xr);
    cudaGetSymbolAddress((void**)&beta,  g_beta);
    cudaGetSymbolAddress((void**)&alpha, g_alpha);
    cudaGetSymbolAddress((void**)&wt,    g_wt);

    cudaFuncSetAttribute(gemm_tc, cudaFuncAttributeMaxDynamicSharedMemorySize, GEMM_SMEM);

    float* wtq = wt + 0ull * KD_ * HID_;
    float* wtk = wt + 1ull * KD_ * HID_;
    float* wtv = wt + 2ull * KD_ * HID_;
    float* wtg = wt + 3ull * KD_ * HID_;
    float* wto = wt + 4ull * KD_ * HID_;

    dim3 tb(32, 8), tg(2048 / 32, 2048 / 32);
    transpose_cvt<<<tg, tb>>>(Wq, wtq, HID_, KD_);
    transpose_cvt<<<tg, tb>>>(Wk, wtk, HID_, KD_);
    transpose_cvt<<<tg, tb>>>(Wv, wtv, HID_, KD_);
    transpose_cvt<<<tg, tb>>>(Wg, wtg, HID_, KD_);
    transpose_cvt<<<tg, tb>>>(Wo, wto, KD_, HID_);

    cvt_kernel<<<(MM_ * HID_) / (256 * 4), 256>>>(x, xr);

    dim3 gg(KD_ / 128, MM_ / 128);
    gemm_tc<<<gg, 256, GEMM_SMEM>>>(xr, wtq, qpre, MM_, KD_, HID_);
    gemm_tc<<<gg, 256, GEMM_SMEM>>>(xr, wtk, kpre, MM_, KD_, HID_);
    gemm_tc<<<gg, 256, GEMM_SMEM>>>(xr, wtv, vpre, MM_, KD_, HID_);
    gemm_tc<<<gg, 256, GEMM_SMEM>>>(xr, wtg, gbuf, MM_, KD_, HID_);

    bg_kernel<<<MM_ / 8, 256>>>(x, Wb, bb, Wgk, bgk, A_log, dt_bias, beta, alpha);

    conv_rope_kernel<<<BB_ * TT_ * HH_, 128>>>(qpre, cqw, cqb, qr);
    conv_rope_kernel<<<BB_ * TT_ * HH_, 128>>>(kpre, ckw, ckb, kr);
    conv_silu_kernel<<<(MM_ * KD_) / 256, 256>>>(vpre, cvw, cvb, vc);

    scan_kernel<<<BB_ * HH_, 256>>>(qr, kr, vc, gbuf, alpha, beta, Dp, onorm_w, act);

    gemm_tc<<<dim3(HID_ / 128, MM_ / 128), 256, GEMM_SMEM>>>(act, wto, (float*)d_out, MM_, HID_, KD_);
}

// round 7
// speedup vs baseline: 1.9035x; 1.0670x over previous
#include <cuda_runtime.h>
#include <cuda_bf16.h>
#include <math.h>
#include <stdint.h>

// Problem constants
#define BB_   2
#define TT_   2048
#define HID_  2048
#define HH_   16
#define DH_   128
#define KD_   2048          // H*Dh
#define MM_   (BB_*TT_)     // 4096
#define KCONV 4

// ---------------- scratch (device globals; no allocation APIs) ----------------
__device__ float g_qpre[MM_*KD_];
__device__ float g_kpre[MM_*KD_];
__device__ float g_vpre[MM_*KD_];
__device__ float g_gbuf[MM_*KD_];
__device__ float g_qr [MM_*KD_];
__device__ float g_kr [MM_*KD_];
__device__ float g_vc [MM_*KD_];
__device__ float g_beta [MM_*HH_];
__device__ float g_alpha[MM_*HH_];
__device__ __align__(16) __nv_bfloat16 g_xhi[MM_*HID_];
__device__ __align__(16) __nv_bfloat16 g_xlo[MM_*HID_];
__device__ __align__(16) __nv_bfloat16 g_ahi[MM_*KD_];   // scan output hi
__device__ __align__(16) __nv_bfloat16 g_alo[MM_*KD_];   // scan output lo
__device__ __align__(16) __nv_bfloat16 g_whi[5 * KD_ * HID_];
__device__ __align__(16) __nv_bfloat16 g_wlo[5 * KD_ * HID_];

// ---------------- helpers ----------------
__device__ __forceinline__ uint32_t smem_u32(const void* p) {
    uint32_t a;
    asm("{ .reg .u64 t; cvta.to.shared.u64 t, %1; cvt.u32.u64 %0, t; }" : "=r"(a) : "l"(p));
    return a;
}
__device__ __forceinline__ void cp_async16(uint32_t dst, const void* src) {
    asm volatile("cp.async.cg.shared.global [%0], [%1], 16;" :: "r"(dst), "l"(src) : "memory");
}
__device__ __forceinline__ void cp_commit() {
    asm volatile("cp.async.commit_group;" ::: "memory");
}
__device__ __forceinline__ void mma_bf16(float* c, const uint32_t* a, const uint32_t* b) {
    asm volatile(
        "mma.sync.aligned.m16n8k16.row.col.f32.bf16.bf16.f32 "
        "{%0,%1,%2,%3}, {%4,%5,%6,%7}, {%8,%9}, {%0,%1,%2,%3};"
        : "+f"(c[0]), "+f"(c[1]), "+f"(c[2]), "+f"(c[3])
        : "r"(a[0]), "r"(a[1]), "r"(a[2]), "r"(a[3]), "r"(b[0]), "r"(b[1]));
}
__device__ __forceinline__ void split_bf16(float v, __nv_bfloat16& h, __nv_bfloat16& l) {
    h = __float2bfloat16(v);
    l = __float2bfloat16(v - __bfloat162float(h));
}

// ---------------- x -> bf16 hi/lo split ----------------
__global__ __launch_bounds__(256)
void cvt_split(const float* __restrict__ in,
               __nv_bfloat16* __restrict__ hi, __nv_bfloat16* __restrict__ lo)
{
    size_t i = ((size_t)blockIdx.x * 256 + threadIdx.x) * 4;
    float4 v = *(const float4*)(in + i);
    __nv_bfloat16 h0, l0, h1, l1, h2, l2, h3, l3;
    split_bf16(v.x, h0, l0); split_bf16(v.y, h1, l1);
    split_bf16(v.z, h2, l2); split_bf16(v.w, h3, l3);
    __nv_bfloat162* ph = (__nv_bfloat162*)(hi + i);
    __nv_bfloat162* pl = (__nv_bfloat162*)(lo + i);
    ph[0] = __nv_bfloat162(h0, h1); ph[1] = __nv_bfloat162(h2, h3);
    pl[0] = __nv_bfloat162(l0, l1); pl[1] = __nv_bfloat162(l2, l3);
}

// ---------------- weight transpose + bf16 hi/lo split ----------------
__global__ __launch_bounds__(256)
void transpose_split(const float* __restrict__ W,
                     __nv_bfloat16* __restrict__ Whi, __nv_bfloat16* __restrict__ Wlo,
                     int K, int N)
{
    __shared__ float t[32][33];
    const int k0 = blockIdx.y * 32, n0 = blockIdx.x * 32;
    const int x = threadIdx.x, y = threadIdx.y;    // (32, 8)
    #pragma unroll
    for (int j = 0; j < 32; j += 8)
        t[y + j][x] = W[(size_t)(k0 + y + j) * N + n0 + x];
    __syncthreads();
    #pragma unroll
    for (int j = 0; j < 32; j += 8) {
        float v = t[x][y + j];
        __nv_bfloat16 h, l;
        split_bf16(v, h, l);
        size_t o = (size_t)(n0 + y + j) * K + k0 + x;
        Whi[o] = h; Wlo[o] = l;
    }
}

// ---------------- bf16x3 GEMM: C[M,N] = A[M,K] @ Bt[N,K]^T (fp32-accurate) ----------------
// A = Ahi+Alo, B = Bhi+Blo (bf16 planes). C += Ahi*Bhi + Ahi*Blo + Alo*Bhi.
// CTA 128x128, K chunks of 32, cp.async double buffered.
// 8 warps = 2(M) x 4(N); warp tile 64x32 = 4x4 m16n8k16 frags (2 ksteps/chunk).
#define BPAD 40                                   // bf16 row stride (80 bytes)
#define BBUF_BYTES (128 * BPAD * 2)               // 10240
#define BSTAGE (4 * BBUF_BYTES)                   // Ahi,Alo,Bhi,Blo: 40960
#define GEMM_SMEM (2 * BSTAGE)                    // 81920

__global__ __launch_bounds__(256)
void gemm_bf16x3(const __nv_bfloat16* __restrict__ Ahi, const __nv_bfloat16* __restrict__ Alo,
                 const __nv_bfloat16* __restrict__ Bhi, const __nv_bfloat16* __restrict__ Blo,
                 float* __restrict__ C, int M, int N, int K)
{
    extern __shared__ __align__(128) char dynsmem[];
    const uint32_t sbase = smem_u32(dynsmem);
    const int tid = threadIdx.x;
    const int wid = tid >> 5, lane = tid & 31;
    const int gid = lane >> 2, tig = lane & 3;
    const int wm = wid >> 2, wn = wid & 3;
    const int bx = blockIdx.x, by = blockIdx.y;

    const __nv_bfloat16* Ah = Ahi + (size_t)by * 128 * K;
    const __nv_bfloat16* Al = Alo + (size_t)by * 128 * K;
    const __nv_bfloat16* Bh = Bhi + (size_t)bx * 128 * K;
    const __nv_bfloat16* Bl = Blo + (size_t)bx * 128 * K;

    float acc[4][4][4];
    #pragma unroll
    for (int mt = 0; mt < 4; mt++)
        #pragma unroll
        for (int nt = 0; nt < 4; nt++)
            #pragma unroll
            for (int r = 0; r < 4; r++) acc[mt][nt][r] = 0.f;

    const int srow = tid >> 1;                       // 0..127
    const int sg0  = (tid & 1) * 2;                  // 0 or 2 (16B segments)
    const uint32_t dbase = (uint32_t)(srow * 80 + sg0 * 16);

    const int nchunk = K >> 5;

    // stage chunk 0 -> buffer 0
    {
        const size_t so = (size_t)srow * K + sg0 * 8;
        uint32_t d = sbase + dbase;
        cp_async16(d,                  Ah + so); cp_async16(d + 16,                  Ah + so + 8);
        cp_async16(d + BBUF_BYTES,     Al + so); cp_async16(d + BBUF_BYTES + 16,     Al + so + 8);
        cp_async16(d + 2*BBUF_BYTES,   Bh + so); cp_async16(d + 2*BBUF_BYTES + 16,   Bh + so + 8);
        cp_async16(d + 3*BBUF_BYTES,   Bl + so); cp_async16(d + 3*BBUF_BYTES + 16,   Bl + so + 8);
        cp_commit();
    }

    for (int i = 0; i < nchunk; i++) {
        const int buf = i & 1;
        if (i + 1 < nchunk) {
            const int nb = buf ^ 1;
            const size_t so = (size_t)srow * K + (i + 1) * 32 + sg0 * 8;
            uint32_t d = sbase + (uint32_t)nb * BSTAGE + dbase;
            cp_async16(d,                Ah + so); cp_async16(d + 16,                Ah + so + 8);
            cp_async16(d + BBUF_BYTES,   Al + so); cp_async16(d + BBUF_BYTES + 16,   Al + so + 8);
            cp_async16(d + 2*BBUF_BYTES, Bh + so); cp_async16(d + 2*BBUF_BYTES + 16, Bh + so + 8);
            cp_async16(d + 3*BBUF_BYTES, Bl + so); cp_async16(d + 3*BBUF_BYTES + 16, Bl + so + 8);
            cp_commit();
            asm volatile("cp.async.wait_group 1;" ::: "memory");
        } else {
            asm volatile("cp.async.wait_group 0;" ::: "memory");
        }
        __syncthreads();

        const uint32_t* pAh = (const uint32_t*)(dynsmem + (size_t)buf * BSTAGE);
        const uint32_t* pAl = pAh + BBUF_BYTES / 4;
        const uint32_t* pBh = pAl + BBUF_BYTES / 4;
        const uint32_t* pBl = pBh + BBUF_BYTES / 4;

        #pragma unroll
        for (int s = 0; s < 2; s++) {
            const int kh = s * 8;                   // uint32 offset within row (k/2)
            uint32_t ah[4][4], al[4][4];
            #pragma unroll
            for (int mt = 0; mt < 4; mt++) {
                const int m0 = wm * 64 + mt * 16 + gid;
                const int i00 = m0 * 20 + kh + tig;
                const int i10 = (m0 + 8) * 20 + kh + tig;
                ah[mt][0] = pAh[i00];     ah[mt][1] = pAh[i10];
                ah[mt][2] = pAh[i00 + 4]; ah[mt][3] = pAh[i10 + 4];
                al[mt][0] = pAl[i00];     al[mt][1] = pAl[i10];
                al[mt][2] = pAl[i00 + 4]; al[mt][3] = pAl[i10 + 4];
            }
            uint32_t bh[4][2], bl[4][2];
            #pragma unroll
            for (int nt = 0; nt < 4; nt++) {
                const int n0 = wn * 32 + nt * 8 + gid;
                const int ib = n0 * 20 + kh + tig;
                bh[nt][0] = pBh[ib]; bh[nt][1] = pBh[ib + 4];
                bl[nt][0] = pBl[ib]; bl[nt][1] = pBl[ib + 4];
            }
            #pragma unroll
            for (int mt = 0; mt < 4; mt++)
                #pragma unroll
                for (int nt = 0; nt < 4; nt++) {
                    mma_bf16(acc[mt][nt], ah[mt], bh[nt]);
                    mma_bf16(acc[mt][nt], ah[mt], bl[nt]);
                    mma_bf16(acc[mt][nt], al[mt], bh[nt]);
                }
        }
        __syncthreads();
    }

    #pragma unroll
    for (int mt = 0; mt < 4; mt++) {
        const int r0 = by * 128 + wm * 64 + mt * 16 + gid;
        #pragma unroll
        for (int nt = 0; nt < 4; nt++) {
            const int cc = bx * 128 + wn * 32 + nt * 8 + tig * 2;
            *(float2*)(C + (size_t)r0 * N + cc)       = make_float2(acc[mt][nt][0], acc[mt][nt][1]);
            *(float2*)(C + (size_t)(r0 + 8) * N + cc) = make_float2(acc[mt][nt][2], acc[mt][nt][3]);
        }
    }
}

// ---------------- beta / alpha (x@Wb, x@Wgk fused, N=16 each) ----------------
__global__ __launch_bounds__(256)
void bg_kernel(const float* __restrict__ x,
               const float* __restrict__ Wb,  const float* __restrict__ bb,
               const float* __restrict__ Wgk, const float* __restrict__ bgk,
               const float* __restrict__ A_log, const float* __restrict__ dt_bias,
               float* __restrict__ beta, float* __restrict__ alpha)
{
    const int warp = threadIdx.x >> 5;
    const int lane = threadIdx.x & 31;
    const int m = blockIdx.x * 8 + warp;
    const float* xr = x + (size_t)m * HID_;
    const float* W  = (lane < 16) ? Wb : Wgk;
    const int c = lane & 15;

    float acc0 = 0.f, acc1 = 0.f;
    for (int kk = 0; kk < HID_; kk += 4) {
        float4 xv = *(const float4*)(xr + kk);
        acc0 = fmaf(xv.x, W[(kk + 0) * HH_ + c], acc0);
        acc1 = fmaf(xv.y, W[(kk + 1) * HH_ + c], acc1);
        acc0 = fmaf(xv.z, W[(kk + 2) * HH_ + c], acc0);
        acc1 = fmaf(xv.w, W[(kk + 3) * HH_ + c], acc1);
    }
    float acc = acc0 + acc1;
    if (lane < 16) {
        beta[(size_t)m * HH_ + c] = 1.f / (1.f + expf(-(acc + bb[c])));
    } else {
        float vv = acc + bgk[c] + dt_bias[c];
        float sp = fmaxf(vv, 0.f) + log1pf(expf(-fabsf(vv)));   // softplus, stable
        alpha[(size_t)m * HH_ + c] = expf(-expf(A_log[c]) * sp);
    }
}

// ---------------- causal depthwise conv(K=4) + SiLU (for v) ----------------
__global__ __launch_bounds__(256)
void conv_silu_kernel(const float* __restrict__ pre, const float* __restrict__ w,
                      const float* __restrict__ bias, float* __restrict__ out)
{
    size_t idx = (size_t)blockIdx.x * 256 + threadIdx.x;   // over MM_*KD_
    int c = (int)(idx & (KD_ - 1));
    size_t m = idx >> 11;
    int t = (int)(m & (TT_ - 1));
    int b = (int)(m >> 11);
    const float* pb = pre + ((size_t)b * TT_) * KD_ + c;
    float acc = bias[c];
    #pragma unroll
    for (int j = 0; j < KCONV; j++) {
        int tt = t - (KCONV - 1) + j;
        if (tt >= 0) acc = fmaf(pb[(size_t)tt * KD_], w[c * KCONV + j], acc);
    }
    out[idx] = acc / (1.f + expf(-acc));
}

// ---------------- conv + SiLU + RoPE + L2 norm (for q and k) ----------------
__global__ __launch_bounds__(128)
void conv_rope_kernel(const float* __restrict__ pre, const float* __restrict__ w,
                      const float* __restrict__ bias, float* __restrict__ out)
{
    __shared__ float sv[DH_];
    __shared__ float swarp[4];
    const int bid = blockIdx.x;            // b*T*H + t*H + h
    const int h = bid & (HH_ - 1);
    const int bt = bid >> 4;
    const int t = bt & (TT_ - 1);
    const int b = bt >> 11;
    const int d = threadIdx.x;
    const int c = h * DH_ + d;

    const float* pb = pre + ((size_t)b * TT_) * KD_ + c;
    float acc = bias[c];
    #pragma unroll
    for (int j = 0; j < KCONV; j++) {
        int tt = t - (KCONV - 1) + j;
        if (tt >= 0) acc = fmaf(pb[(size_t)tt * KD_], w[c * KCONV + j], acc);
    }
    sv[d] = acc / (1.f + expf(-acc));
    __syncthreads();

    const int i = d & 63;
    float x1 = sv[2 * i], x2 = sv[2 * i + 1];
    const int fidx = (2 * i) & 63;                       // reference's (2i) % 64 quirk
    float inv = exp2f(-(float)fidx * (13.287712379549449f / 64.0f)); // 10000^(-fidx/64)
    float th = (float)t * inv;
    float cs = cosf(th), sn = sinf(th);
    float r = (d < 64) ? (x1 * cs - x2 * sn) : (x1 * sn + x2 * cs);

    float ss = r * r;
    #pragma unroll
    for (int off = 16; off; off >>= 1) ss += __shfl_down_sync(0xffffffffu, ss, off);
    if ((d & 31) == 0) swarp[d >> 5] = ss;
    __syncthreads();
    float tot = swarp[0] + swarp[1] + swarp[2] + swarp[3];
    float nrm = fmaxf(sqrtf(tot), 1e-12f);
    out[((size_t)(b * TT_ + t) * HH_ + h) * DH_ + d] = r / nrm;
}

// ---------------- sequential gated-delta scan + fused output norm/gate ----------------
// Prefetched loads (t+1 hidden behind t's compute); split reductions across halves.
__global__ __launch_bounds__(256)
void scan_kernel(const float* __restrict__ q, const float* __restrict__ k,
                 const float* __restrict__ v, const float* __restrict__ g,
                 const float* __restrict__ alpha, const float* __restrict__ beta,
                 const float* __restrict__ Dp, const float* __restrict__ onw,
                 __nv_bfloat16* __restrict__ acth, __nv_bfloat16* __restrict__ actl)
{
    __shared__ float sq[DH_], sk[DH_], sv[DH_], sg[DH_], sw[DH_];
    __shared__ float red_o[16 * DH_];
    __shared__ float red_s[16 * DH_];
    __shared__ float s_sk[DH_];
    __shared__ float s_qk[4], s_rms[4], s_ab[2];

    const int tid = threadIdx.x;
    const int bh = blockIdx.x;
    const int h = bh & (HH_ - 1);
    const int b = bh >> 4;
    const int tx = tid & 15, ty = tid >> 4;
    const int dbase = ty * 8, ebase = tx * 8;

    float S[8][8];
    #pragma unroll
    for (int i = 0; i < 8; i++)
        #pragma unroll
        for (int j = 0; j < 8; j++) S[i][j] = 0.f;

    if (tid < DH_) sw[tid] = onw[tid];
    const float Dph = Dp[h];
    const size_t vecbase = ((size_t)(b * TT_) * HH_ + h) * DH_;

    // prefetch t=0
    float rq = 0.f, rk = 0.f, rv = 0.f, rg = 0.f, ra = 0.f, rb2 = 0.f;
    if (tid < DH_) {
        rq = q[vecbase + tid]; rk = k[vecbase + tid];
        rv = v[vecbase + tid]; rg = g[vecbase + tid];
    }
    if (tid == 0) {
        size_t si = (size_t)(b * TT_) * HH_ + h;
        ra = alpha[si]; rb2 = beta[si];
    }

    for (int t = 0; t < TT_; t++) {
        const size_t base = vecbase + (size_t)t * (HH_ * DH_);
        if (tid < DH_) { sq[tid] = rq; sk[tid] = rk; sv[tid] = rv; sg[tid] = rg; }
        if (tid == 0)  { s_ab[0] = ra; s_ab[1] = rb2; }
        __syncthreads();                       // (1) vectors ready

        // prefetch t+1 (latency hidden behind matvec + reductions)
        if (t + 1 < TT_) {
            const size_t nb = base + (HH_ * DH_);
            if (tid < DH_) {
                rq = q[nb + tid]; rk = k[nb + tid];
                rv = v[nb + tid]; rg = g[nb + tid];
            }
            if (tid == 0) {
                size_t si = (size_t)(b * TT_ + t + 1) * HH_ + h;
                ra = alpha[si]; rb2 = beta[si];
            }
        }

        float qv[8], kv[8];
        #pragma unroll
        for (int i = 0; i < 8; i++) qv[i] = sq[dbase + i];
        #pragma unroll
        for (int j = 0; j < 8; j++) kv[j] = sk[ebase + j];

        float po[8] = {0,0,0,0,0,0,0,0};
        float ps[8] = {0,0,0,0,0,0,0,0};
        #pragma unroll
        for (int i = 0; i < 8; i++) {
            float qi = qv[i];
            #pragma unroll
            for (int j = 0; j < 8; j++) {
                float s = S[i][j];
                po[j] = fmaf(qi, s, po[j]);       // o partial
                ps[i] = fmaf(s, kv[j], ps[i]);    // Sk partial
            }
        }
        *(float4*)&red_o[ty * DH_ + ebase]     = make_float4(po[0], po[1], po[2], po[3]);
        *(float4*)&red_o[ty * DH_ + ebase + 4] = make_float4(po[4], po[5], po[6], po[7]);
        *(float4*)&red_s[tx * DH_ + dbase]     = make_float4(ps[0], ps[1], ps[2], ps[3]);
        *(float4*)&red_s[tx * DH_ + dbase + 4] = make_float4(ps[4], ps[5], ps[6], ps[7]);
        __syncthreads();                       // (2) partials staged

        float o = 0.f;
        if (tid < DH_) {
            #pragma unroll
            for (int xx = 0; xx < 16; xx++) o += red_o[xx * DH_ + tid];
            float qq = sq[tid] * sk[tid];
            #pragma unroll
            for (int off = 16; off; off >>= 1) qq += __shfl_down_sync(0xffffffffu, qq, off);
            if ((tid & 31) == 0) s_qk[tid >> 5] = qq;
        } else {
            const int td = tid - DH_;
            float skd = 0.f;
            #pragma unroll
            for (int xx = 0; xx < 16; xx++) skd += red_s[xx * DH_ + td];
            s_sk[td] = skd;
        }
        __syncthreads();                       // (3) Sk + qk ready

        const float aA = s_ab[0];
        const float bB = s_ab[1];

        if (tid < DH_) {
            float qkv = s_qk[0] + s_qk[1] + s_qk[2] + s_qk[3];
            o = fmaf(Dph * qkv, sv[tid], o);
            float oo = o * o;
            #pragma unroll
            for (int off = 16; off; off >>= 1) oo += __shfl_down_sync(0xffffffffu, oo, off);
            if ((tid & 31) == 0) s_rms[tid >> 5] = oo;
        }

        // state update: S = aA*S + (bB*v_d - aA*bB*Sk_d) * k_e
        float cf[8];
        #pragma unroll
        for (int i = 0; i < 8; i++)
            cf[i] = bB * sv[dbase + i] - aA * bB * s_sk[dbase + i];
        #pragma unroll
        for (int i = 0; i < 8; i++) {
            float c = cf[i];
            #pragma unroll
            for (int j = 0; j < 8; j++)
                S[i][j] = fmaf(aA, S[i][j], c * kv[j]);
        }
        __syncthreads();                       // (4) rms staged, update done

        if (tid < DH_) {
            float rsum = s_rms[0] + s_rms[1] + s_rms[2] + s_rms[3];
            float rr = rsqrtf(rsum * (1.f / (float)DH_) + 1e-6f);
            float valn = o * rr * sw[tid];
            float sig = 1.f / (1.f + expf(-valn));
            float val = sg[tid] * valn * sig;
            __nv_bfloat16 hh, ll;
            split_bf16(val, hh, ll);
            acth[base + tid] = hh;
            actl[base + tid] = ll;
        }
    }
}

// ---------------- launch ----------------
extern "C" void kernel_launch(void* const* d_in, const int* in_sizes, int n_in,
                              void* d_out, int out_size)
{
    const float* x       = (const float*)d_in[0];
    const float* Wq      = (const float*)d_in[1];
    const float* Wk      = (const float*)d_in[2];
    const float* Wv      = (const float*)d_in[3];
    const float* Wg      = (const float*)d_in[4];
    const float* Wo      = (const float*)d_in[5];
    const float* Wb      = (const float*)d_in[6];
    const float* bb      = (const float*)d_in[7];
    const float* Wgk     = (const float*)d_in[8];
    const float* bgk     = (const float*)d_in[9];
    const float* cqw     = (const float*)d_in[10];
    const float* cqb     = (const float*)d_in[11];
    const float* ckw     = (const float*)d_in[12];
    const float* ckb     = (const float*)d_in[13];
    const float* cvw     = (const float*)d_in[14];
    const float* cvb     = (const float*)d_in[15];
    const float* A_log   = (const float*)d_in[16];
    const float* Dp      = (const float*)d_in[17];
    const float* dt_bias = (const float*)d_in[18];
    const float* onorm_w = (const float*)d_in[19];

    float *qpre, *kpre, *vpre, *gbuf, *qr, *kr, *vc, *beta, *alpha;
    __nv_bfloat16 *xhi, *xlo, *ahi, *alo, *whi, *wlo;
    cudaGetSymbolAddress((void**)&qpre,  g_qpre);
    cudaGetSymbolAddress((void**)&kpre,  g_kpre);
    cudaGetSymbolAddress((void**)&vpre,  g_vpre);
    cudaGetSymbolAddress((void**)&gbuf,  g_gbuf);
    cudaGetSymbolAddress((void**)&qr,    g_qr);
    cudaGetSymbolAddress((void**)&kr,    g_kr);
    cudaGetSymbolAddress((void**)&vc,    g_vc);
    cudaGetSymbolAddress((void**)&beta,  g_beta);
    cudaGetSymbolAddress((void**)&alpha, g_alpha);
    cudaGetSymbolAddress((void**)&xhi,   g_xhi);
    cudaGetSymbolAddress((void**)&xlo,   g_xlo);
    cudaGetSymbolAddress((void**)&ahi,   g_ahi);
    cudaGetSymbolAddress((void**)&alo,   g_alo);
    cudaGetSymbolAddress((void**)&whi,   g_whi);
    cudaGetSymbolAddress((void**)&wlo,   g_wlo);

    cudaFuncSetAttribute(gemm_bf16x3, cudaFuncAttributeMaxDynamicSharedMemorySize, GEMM_SMEM);

    __nv_bfloat16* whq = whi + 0ull * KD_ * HID_;  __nv_bfloat16* wlq = wlo + 0ull * KD_ * HID_;
    __nv_bfloat16* whk = whi + 1ull * KD_ * HID_;  __nv_bfloat16* wlk = wlo + 1ull * KD_ * HID_;
    __nv_bfloat16* whv = whi + 2ull * KD_ * HID_;  __nv_bfloat16* wlv = wlo + 2ull * KD_ * HID_;
    __nv_bfloat16* whg = whi + 3ull * KD_ * HID_;  __nv_bfloat16* wlg = wlo + 3ull * KD_ * HID_;
    __nv_bfloat16* who = whi + 4ull * KD_ * HID_;  __nv_bfloat16* wlho = wlo + 4ull * KD_ * HID_;

    dim3 tb(32, 8), tg(2048 / 32, 2048 / 32);
    transpose_split<<<tg, tb>>>(Wq, whq, wlq, HID_, KD_);
    transpose_split<<<tg, tb>>>(Wk, whk, wlk, HID_, KD_);
    transpose_split<<<tg, tb>>>(Wv, whv, wlv, HID_, KD_);
    transpose_split<<<tg, tb>>>(Wg, whg, wlg, HID_, KD_);
    transpose_split<<<tg, tb>>>(Wo, who, wlho, KD_, HID_);

    cvt_split<<<(MM_ * HID_) / (256 * 4), 256>>>(x, xhi, xlo);

    dim3 gg(KD_ / 128, MM_ / 128);
    gemm_bf16x3<<<gg, 256, GEMM_SMEM>>>(xhi, xlo, whq, wlq, qpre, MM_, KD_, HID_);
    gemm_bf16x3<<<gg, 256, GEMM_SMEM>>>(xhi, xlo, whk, wlk, kpre, MM_, KD_, HID_);
    gemm_bf16x3<<<gg, 256, GEMM_SMEM>>>(xhi, xlo, whv, wlv, vpre, MM_, KD_, HID_);
    gemm_bf16x3<<<gg, 256, GEMM_SMEM>>>(xhi, xlo, whg, wlg, gbuf, MM_, KD_, HID_);

    bg_kernel<<<MM_ / 8, 256>>>(x, Wb, bb, Wgk, bgk, A_log, dt_bias, beta, alpha);

    conv_rope_kernel<<<BB_ * TT_ * HH_, 128>>>(qpre, cqw, cqb, qr);
    conv_rope_kernel<<<BB_ * TT_ * HH_, 128>>>(kpre, ckw, ckb, kr);
    conv_silu_kernel<<<(MM_ * KD_) / 256, 256>>>(vpre, cvw, cvb, vc);

    scan_kernel<<<BB_ * HH_, 256>>>(qr, kr, vc, gbuf, alpha, beta, Dp, onorm_w, ahi, alo);

    gemm_bf16x3<<<dim3(HID_ / 128, MM_ / 128), 256, GEMM_SMEM>>>(ahi, alo, who, wlho,
                                                                 (float*)d_out, MM_, HID_, KD_);
}